// round 10
// baseline (speedup 1.0000x reference)
#include <cuda_runtime.h>
#include <cuda_fp16.h>
#include <cstdint>

#define N_MAX 100000
#define N_PAD 100096
#define E_MAX 400000

// ---------------- scratch ---------------------------------------------------
__device__ __align__(16) __half g_a1[(size_t)N_PAD * 256];   // [agg1|x] fp16
__device__ __align__(16) __half g_h [(size_t)N_PAD * 256];   // hidden fp16
__device__ __align__(16) __half g_t2[(size_t)N_MAX * 128];   // [t | o2] fp16
__device__ __align__(16) __half g_W1[256 * 256];             // [n][k]
__device__ __align__(16) __half g_W2[128 * 256];             // [n][k], n=[W2l|W2r]
__device__ int g_src[E_MAX], g_dst[E_MAX];
__device__ int g_cnt[N_MAX];            // zeroed by scan for next replay
__device__ int g_rowptr[N_MAX + 1], g_cursor[N_MAX], g_esrc[E_MAX];
__device__ volatile int g_flag[256];    // lookback status; zeroed by fill for next replay
__device__ volatile int g_bsum[256];
__device__ volatile int g_bpre[256];

// ---------------- helpers ---------------------------------------------------
__device__ __forceinline__ uint32_t smem_u32(const void* p) {
    uint32_t a;
    asm("{ .reg .u64 t; cvta.to.shared.u64 t, %1; cvt.u32.u64 %0, t; }" : "=r"(a) : "l"(p));
    return a;
}

__device__ __forceinline__ void cp16(uint32_t dst, const void* src) {
    asm volatile("cp.async.cg.shared.global [%0], [%1], 16;" :: "r"(dst), "l"(src) : "memory");
}
__device__ __forceinline__ void cp_commit() {
    asm volatile("cp.async.commit_group;" ::: "memory");
}
__device__ __forceinline__ void cp_wait0() {
    asm volatile("cp.async.wait_group 0;" ::: "memory");
}

__device__ __forceinline__ void ldsm_x4(uint32_t& r0, uint32_t& r1, uint32_t& r2, uint32_t& r3,
                                        uint32_t addr) {
    asm volatile("ldmatrix.sync.aligned.m8n8.x4.shared.b16 {%0,%1,%2,%3}, [%4];"
                 : "=r"(r0), "=r"(r1), "=r"(r2), "=r"(r3) : "r"(addr));
}

__device__ __forceinline__ void mma_f16(float* c, const uint32_t* a, uint32_t b0, uint32_t b1) {
    asm volatile(
        "mma.sync.aligned.m16n8k16.row.col.f32.f16.f16.f32 "
        "{%0,%1,%2,%3}, {%4,%5,%6,%7}, {%8,%9}, {%0,%1,%2,%3};"
        : "+f"(c[0]), "+f"(c[1]), "+f"(c[2]), "+f"(c[3])
        : "r"(a[0]), "r"(a[1]), "r"(a[2]), "r"(a[3]), "r"(b0), "r"(b1));
}

// ---------------- L1: convert edges (int32) + histogram + all fp16 conversions
__global__ void prep_kernel(const int* __restrict__ ei, int E, int Nn,
                            const float* __restrict__ W1l, const float* __restrict__ W1r,
                            const float* __restrict__ W2l, const float* __restrict__ W2r,
                            const float* __restrict__ x) {
    const int EB = ((E + 255) / 256) * 256;
    int gid = blockIdx.x * 256 + threadIdx.x;
    if (gid < EB) {
        int e = gid;
        if (e < E) {
            int s = ei[e], d = ei[E + e];
            if (s < 0) s = 0; if (s >= Nn) s = Nn - 1;
            if (d < 0) d = 0; if (d >= Nn) d = Nn - 1;
            g_src[e] = s;
            g_dst[e] = d;
            atomicAdd(&g_cnt[d], 1);
        }
        return;
    }
    int g = gid - EB;
    if (g < 65536) {                         // W1 transposed
        int n = g & 255, k = g >> 8;
        float v = (k < 128) ? W1l[(size_t)k * 256 + n] : W1r[(size_t)(k - 128) * 256 + n];
        g_W1[n * 256 + k] = __float2half_rn(v);
    } else if (g < 98304) {                  // W2, n = [W2l|W2r]
        int q = g - 65536;
        int n = q & 127, k = q >> 7;
        float v = (n < 64) ? W2l[(size_t)k * 64 + n] : W2r[(size_t)k * 64 + (n - 64)];
        g_W2[n * 256 + k] = __float2half_rn(v);
    } else {                                 // x -> fp16, cols 128..255 of A1
        int q = g - 98304;
        if (q >= Nn * 32) return;
        int node = q >> 5;
        int c = (q & 31) * 4;
        float4 v = *(const float4*)(x + (size_t)node * 128 + c);
        __half2 p0 = __floats2half2_rn(v.x, v.y);
        __half2 p1 = __floats2half2_rn(v.z, v.w);
        *(uint2*)(g_a1 + (size_t)node * 256 + 128 + c) =
            make_uint2(*(uint32_t*)&p0, *(uint32_t*)&p1);
    }
}

// ---------------- L2: single-kernel decoupled-lookback scan -------------------
// rowptr/cursor = exclusive scan of g_cnt; also re-zeroes g_cnt for next replay.
__global__ void scan_kernel(int Nn, int E) {
    __shared__ int s[512];
    __shared__ int s_off;
    const int bid = blockIdx.x;
    const int i = bid * 512 + threadIdx.x;
    int v = (i < Nn) ? g_cnt[i] : 0;
    s[threadIdx.x] = v;
    __syncthreads();
#pragma unroll
    for (int off = 1; off < 512; off <<= 1) {
        int t = (threadIdx.x >= off) ? s[threadIdx.x - off] : 0;
        __syncthreads();
        s[threadIdx.x] += t;
        __syncthreads();
    }
    if (threadIdx.x == 0) {
        int total = s[511];
        g_bsum[bid] = total;
        __threadfence();
        g_flag[bid] = 1;
        int excl = 0;
        for (int j = bid - 1; j >= 0; j--) {
            int f;
            do { f = g_flag[j]; } while (f == 0);
            if (f == 2) { excl += g_bpre[j]; break; }
            excl += g_bsum[j];
        }
        g_bpre[bid] = excl + total;
        __threadfence();
        g_flag[bid] = 2;
        s_off = excl;
    }
    __syncthreads();
    if (i < Nn) {
        int r = s[threadIdx.x] - v + s_off;
        g_rowptr[i] = r;
        g_cursor[i] = r;
        g_cnt[i] = 0;                        // ready for next replay
    }
    if (i == 0) g_rowptr[Nn] = E;
}

// ---------------- L3: fill CSR (+ reset lookback flags for next replay) -------
__global__ void fill_kernel(int E) {
    int e = blockIdx.x * blockDim.x + threadIdx.x;
    if (e < 256) g_flag[e] = 0;              // flags fully consumed by scan
    if (e < E) {
        int pos = atomicAdd(&g_cursor[g_dst[e]], 1);
        g_esrc[pos] = g_src[e];
    }
}

// ---------------- L4: gather-mean agg1 (fp16) ---------------------------------
__global__ void agg1_kernel(int Nn) {
    int warp = (blockIdx.x * blockDim.x + threadIdx.x) >> 5;
    int lane = threadIdx.x & 31;
    if (warp >= Nn) return;
    int s0 = g_rowptr[warp], s1 = g_rowptr[warp + 1];
    float4 acc = make_float4(0.f, 0.f, 0.f, 0.f);
    int e = s0;
    for (; e + 1 < s1; e += 2) {
        int sa = g_esrc[e], sb = g_esrc[e + 1];
        uint2 ua = *(const uint2*)(g_a1 + (size_t)sa * 256 + 128 + lane * 4);
        uint2 ub = *(const uint2*)(g_a1 + (size_t)sb * 256 + 128 + lane * 4);
        float2 a0 = __half22float2(*(__half2*)&ua.x);
        float2 a1 = __half22float2(*(__half2*)&ua.y);
        float2 b0 = __half22float2(*(__half2*)&ub.x);
        float2 b1 = __half22float2(*(__half2*)&ub.y);
        acc.x += a0.x + b0.x; acc.y += a0.y + b0.y;
        acc.z += a1.x + b1.x; acc.w += a1.y + b1.y;
    }
    if (e < s1) {
        int sa = g_esrc[e];
        uint2 ua = *(const uint2*)(g_a1 + (size_t)sa * 256 + 128 + lane * 4);
        float2 a0 = __half22float2(*(__half2*)&ua.x);
        float2 a1 = __half22float2(*(__half2*)&ua.y);
        acc.x += a0.x; acc.y += a0.y; acc.z += a1.x; acc.w += a1.y;
    }
    float inv = 1.f / fmaxf((float)(s1 - s0), 1.f);
    __half2 p0 = __floats2half2_rn(acc.x * inv, acc.y * inv);
    __half2 p1 = __floats2half2_rn(acc.z * inv, acc.w * inv);
    *(uint2*)(g_a1 + (size_t)warp * 256 + lane * 4) =
        make_uint2(*(uint32_t*)&p0, *(uint32_t*)&p1);
}

// ---------------- L5/L6: HMMA fp16 GEMM ---------------------------------------
#define ROWB 144
#define TILE_BYTES (128 * ROWB)

__device__ __forceinline__ void load_one(uint32_t sT, const __half* __restrict__ T,
                                         int row0, int k0, int tid) {
    int row = tid >> 1;
    const char* src = (const char*)(T + (size_t)(row0 + row) * 256 + k0) + (tid & 1) * 64;
    uint32_t d = sT + row * ROWB + (tid & 1) * 64;
#pragma unroll
    for (int j = 0; j < 4; j++) cp16(d + j * 16, src + j * 16);
}

// MODE 1: D[.,256] = [agg1|x] @ W1 ; +b1, relu -> g_h (fp16)
// MODE 2: D[.,128] = h @ [W2l|W2r] ; fp16 -> g_t2 (t cols 0-63, o2 cols 64-127)
template <int MODE>
__global__ __launch_bounds__(256, 2)
void mma_kernel(const float* __restrict__ bias, int Nn) {
    extern __shared__ char sm[];
    const uint32_t smb = smem_u32(sm);
    const uint32_t Abuf[2] = { smb, smb + TILE_BYTES };
    const uint32_t Bbuf[2] = { smb + 2 * TILE_BYTES, smb + 3 * TILE_BYTES };

    const int tid = threadIdx.x;
    const int wid = tid >> 5;
    const int lane = tid & 31;
    const int m0 = blockIdx.x * 128;
    const int n0 = blockIdx.y * 128;

    const __half* A = (MODE == 1) ? g_a1 : g_h;
    const __half* B = (MODE == 1) ? g_W1 : g_W2;

    const int wm = (wid >> 2) * 64;
    const int wn = (wid & 3) * 32;
    const int lrow = lane & 15;
    const int lcol8 = (lane >> 4) * 8;

    float acc[4][4][4];
#pragma unroll
    for (int i = 0; i < 4; i++)
#pragma unroll
        for (int j = 0; j < 4; j++)
#pragma unroll
            for (int q = 0; q < 4; q++) acc[i][j][q] = 0.f;

    load_one(Abuf[0], A, m0, 0, tid);
    load_one(Bbuf[0], B, n0, 0, tid);
    cp_commit();
    cp_wait0();
    __syncthreads();

    for (int s = 0; s < 4; s++) {
        int sn = s + 1;
        if (sn < 4) {
            load_one(Abuf[sn & 1], A, m0, sn * 64, tid);
            load_one(Bbuf[sn & 1], B, n0, sn * 64, tid);
            cp_commit();
        }
        uint32_t sA = Abuf[s & 1], sB = Bbuf[s & 1];
#pragma unroll
        for (int ks = 0; ks < 4; ks++) {
            int kb = ks * 16 + lcol8;
            uint32_t a[4][4], b[2][4];
#pragma unroll
            for (int mt = 0; mt < 4; mt++)
                ldsm_x4(a[mt][0], a[mt][1], a[mt][2], a[mt][3],
                        sA + (wm + mt * 16 + lrow) * ROWB + kb * 2);
#pragma unroll
            for (int p = 0; p < 2; p++)
                ldsm_x4(b[p][0], b[p][1], b[p][2], b[p][3],
                        sB + (wn + p * 16 + lrow) * ROWB + kb * 2);
#pragma unroll
            for (int mt = 0; mt < 4; mt++)
#pragma unroll
                for (int nt = 0; nt < 4; nt++)
                    mma_f16(acc[mt][nt], a[mt], b[nt >> 1][nt & 1], b[nt >> 1][(nt & 1) + 2]);
        }
        if (sn < 4) cp_wait0();
        __syncthreads();
    }

#pragma unroll
    for (int mt = 0; mt < 4; mt++) {
        int r0 = m0 + wm + mt * 16 + (lane >> 2);
#pragma unroll
        for (int nt = 0; nt < 4; nt++) {
            int colL = wn + nt * 8 + (lane & 3) * 2;
            if (MODE == 1) {
                int col = n0 + colL;
                float bb0 = __ldg(bias + col), bb1 = __ldg(bias + col + 1);
#pragma unroll
                for (int h = 0; h < 2; h++) {
                    int r = r0 + h * 8;
                    if (r < Nn) {
                        float v0 = fmaxf(acc[mt][nt][2 * h + 0] + bb0, 0.f);
                        float v1 = fmaxf(acc[mt][nt][2 * h + 1] + bb1, 0.f);
                        __half2 p = __floats2half2_rn(v0, v1);
                        *(uint32_t*)(g_h + (size_t)r * 256 + col) = *(uint32_t*)&p;
                    }
                }
            } else {
#pragma unroll
                for (int h = 0; h < 2; h++) {
                    int r = r0 + h * 8;
                    if (r < Nn) {
                        __half2 p = __floats2half2_rn(acc[mt][nt][2 * h + 0],
                                                      acc[mt][nt][2 * h + 1]);
                        *(uint32_t*)(g_t2 + (size_t)r * 128 + colL) = *(uint32_t*)&p;
                    }
                }
            }
        }
    }
}

// ---------------- L7: agg2 + final fused --------------------------------------
__global__ void agg2_final_kernel(const float* __restrict__ b2,
                                  float* __restrict__ out, int Nn) {
    int warp = (blockIdx.x * blockDim.x + threadIdx.x) >> 5;
    int lane = threadIdx.x & 31;
    if (warp >= Nn) return;
    int s0 = g_rowptr[warp], s1 = g_rowptr[warp + 1];
    float2 acc = make_float2(0.f, 0.f);
    int e = s0;
    for (; e + 1 < s1; e += 2) {
        int sa = g_esrc[e], sb = g_esrc[e + 1];
        uint32_t ua = *(const uint32_t*)(g_t2 + (size_t)sa * 128 + lane * 2);
        uint32_t ub = *(const uint32_t*)(g_t2 + (size_t)sb * 128 + lane * 2);
        float2 fa = __half22float2(*(__half2*)&ua);
        float2 fb = __half22float2(*(__half2*)&ub);
        acc.x += fa.x + fb.x; acc.y += fa.y + fb.y;
    }
    if (e < s1) {
        int sa = g_esrc[e];
        uint32_t ua = *(const uint32_t*)(g_t2 + (size_t)sa * 128 + lane * 2);
        float2 fa = __half22float2(*(__half2*)&ua);
        acc.x += fa.x; acc.y += fa.y;
    }
    float inv = 1.f / fmaxf((float)(s1 - s0), 1.f);
    uint32_t uo = *(const uint32_t*)(g_t2 + (size_t)warp * 128 + 64 + lane * 2);
    float2 o = __half22float2(*(__half2*)&uo);
    float2 bb = *(const float2*)(b2 + lane * 2);
    float2 v = make_float2(acc.x * inv + o.x + bb.x, acc.y * inv + o.y + bb.y);
    *(float2*)(out + (size_t)warp * 64 + lane * 2) = v;
}

// ---------------- launch --------------------------------------------------------
extern "C" void kernel_launch(void* const* d_in, const int* in_sizes, int n_in,
                              void* d_out, int out_size) {
    const float* x   = (const float*)d_in[0];
    const int*   ei  = (const int*)d_in[1];      // staged int32 (verified empirically)
    const float* W1l = (const float*)d_in[2];
    const float* b1  = (const float*)d_in[3];
    const float* W1r = (const float*)d_in[4];
    const float* W2l = (const float*)d_in[5];
    const float* b2  = (const float*)d_in[6];
    const float* W2r = (const float*)d_in[7];
    float*       out = (float*)d_out;

    const int Nn = in_sizes[0] / 128;
    const int E  = in_sizes[1] / 2;
    const int nb = (Nn + 511) / 512;

    const int SMEM = 4 * TILE_BYTES;   // 73728
    cudaFuncSetAttribute(mma_kernel<1>, cudaFuncAttributeMaxDynamicSharedMemorySize, SMEM);
    cudaFuncSetAttribute(mma_kernel<2>, cudaFuncAttributeMaxDynamicSharedMemorySize, SMEM);

    const int EB = ((E + 255) / 256) * 256;
    const int prepThreads = EB + 98304 + Nn * 32;
    prep_kernel<<<(prepThreads + 255) / 256, 256>>>(ei, E, Nn, W1l, W1r, W2l, W2r, x);
    scan_kernel<<<nb, 512>>>(Nn, E);
    fill_kernel<<<(E + 255) / 256, 256>>>(E);
    agg1_kernel<<<(Nn * 32 + 255) / 256, 256>>>(Nn);

    const int grid = (Nn + 127) / 128;
    mma_kernel<1><<<dim3(grid, 2), 256, SMEM>>>(b1, Nn);
    mma_kernel<2><<<dim3(grid, 1), 256, SMEM>>>(b2, Nn);
    agg2_final_kernel<<<(Nn * 32 + 255) / 256, 256>>>(b2, out, Nn);
}

// round 11
// speedup vs baseline: 1.0523x; 1.0523x over previous
#include <cuda_runtime.h>
#include <cuda_fp16.h>
#include <cstdint>

#define N_MAX 100000
#define N_PAD 100096
#define E_MAX 400000

// ---------------- scratch ---------------------------------------------------
__device__ __align__(16) __half g_a1[(size_t)N_PAD * 256];   // [agg1|x] fp16
__device__ __align__(16) __half g_h [(size_t)N_PAD * 256];   // hidden fp16
__device__ __align__(16) __half g_t2[(size_t)N_MAX * 128];   // [t | o2] fp16
__device__ __align__(16) __half g_W1[256 * 256];             // [n][k]
__device__ __align__(16) __half g_W2[128 * 256];             // [n][k], n=[W2l|W2r]
__device__ int g_src[E_MAX], g_dst[E_MAX];
__device__ int g_cnt[N_MAX];            // zeroed by scan for next replay
__device__ int g_rowptr[N_MAX + 1], g_cursor[N_MAX], g_esrc[E_MAX];
__device__ volatile int g_flag[256];    // lookback status; zeroed by fill for next replay
__device__ volatile int g_bsum[256];
__device__ volatile int g_bpre[256];

// ---------------- helpers ---------------------------------------------------
__device__ __forceinline__ uint32_t smem_u32(const void* p) {
    uint32_t a;
    asm("{ .reg .u64 t; cvta.to.shared.u64 t, %1; cvt.u32.u64 %0, t; }" : "=r"(a) : "l"(p));
    return a;
}

__device__ __forceinline__ void cp16(uint32_t dst, const void* src) {
    asm volatile("cp.async.cg.shared.global [%0], [%1], 16;" :: "r"(dst), "l"(src) : "memory");
}
__device__ __forceinline__ void cp_commit() {
    asm volatile("cp.async.commit_group;" ::: "memory");
}
__device__ __forceinline__ void cp_wait0() {
    asm volatile("cp.async.wait_group 0;" ::: "memory");
}

__device__ __forceinline__ void ldsm_x4(uint32_t& r0, uint32_t& r1, uint32_t& r2, uint32_t& r3,
                                        uint32_t addr) {
    asm volatile("ldmatrix.sync.aligned.m8n8.x4.shared.b16 {%0,%1,%2,%3}, [%4];"
                 : "=r"(r0), "=r"(r1), "=r"(r2), "=r"(r3) : "r"(addr));
}

__device__ __forceinline__ void mma_f16(float* c, const uint32_t* a, uint32_t b0, uint32_t b1) {
    asm volatile(
        "mma.sync.aligned.m16n8k16.row.col.f32.f16.f16.f32 "
        "{%0,%1,%2,%3}, {%4,%5,%6,%7}, {%8,%9}, {%0,%1,%2,%3};"
        : "+f"(c[0]), "+f"(c[1]), "+f"(c[2]), "+f"(c[3])
        : "r"(a[0]), "r"(a[1]), "r"(a[2]), "r"(a[3]), "r"(b0), "r"(b1));
}

// ---------------- L1: convert edges (int32) + histogram + fp16 conversions ----
__global__ void prep_kernel(const int* __restrict__ ei, int E, int Nn,
                            const float* __restrict__ W1l, const float* __restrict__ W1r,
                            const float* __restrict__ W2l, const float* __restrict__ W2r,
                            const float* __restrict__ x) {
    const int EB = ((E + 255) / 256) * 256;
    int gid = blockIdx.x * 256 + threadIdx.x;
    if (gid < EB) {
        int e = gid;
        if (e < E) {
            int s = ei[e], d = ei[E + e];
            if (s < 0) s = 0; if (s >= Nn) s = Nn - 1;
            if (d < 0) d = 0; if (d >= Nn) d = Nn - 1;
            g_src[e] = s;
            g_dst[e] = d;
            atomicAdd(&g_cnt[d], 1);
        }
        return;
    }
    int g = gid - EB;
    if (g < 65536) {                         // W1 transposed
        int n = g & 255, k = g >> 8;
        float v = (k < 128) ? W1l[(size_t)k * 256 + n] : W1r[(size_t)(k - 128) * 256 + n];
        g_W1[n * 256 + k] = __float2half_rn(v);
    } else if (g < 98304) {                  // W2, n = [W2l|W2r]
        int q = g - 65536;
        int n = q & 127, k = q >> 7;
        float v = (n < 64) ? W2l[(size_t)k * 64 + n] : W2r[(size_t)k * 64 + (n - 64)];
        g_W2[n * 256 + k] = __float2half_rn(v);
    } else {                                 // x -> fp16, cols 128..255 of A1
        int q = g - 98304;
        if (q >= Nn * 32) return;
        int node = q >> 5;
        int c = (q & 31) * 4;
        float4 v = *(const float4*)(x + (size_t)node * 128 + c);
        __half2 p0 = __floats2half2_rn(v.x, v.y);
        __half2 p1 = __floats2half2_rn(v.z, v.w);
        *(uint2*)(g_a1 + (size_t)node * 256 + 128 + c) =
            make_uint2(*(uint32_t*)&p0, *(uint32_t*)&p1);
    }
}

// ---------------- L2: single-kernel decoupled-lookback scan -------------------
__global__ void scan_kernel(int Nn, int E) {
    __shared__ int s[512];
    __shared__ int s_off;
    const int bid = blockIdx.x;
    const int i = bid * 512 + threadIdx.x;
    int v = (i < Nn) ? g_cnt[i] : 0;
    s[threadIdx.x] = v;
    __syncthreads();
#pragma unroll
    for (int off = 1; off < 512; off <<= 1) {
        int t = (threadIdx.x >= off) ? s[threadIdx.x - off] : 0;
        __syncthreads();
        s[threadIdx.x] += t;
        __syncthreads();
    }
    if (threadIdx.x == 0) {
        int total = s[511];
        g_bsum[bid] = total;
        __threadfence();
        g_flag[bid] = 1;
        int excl = 0;
        for (int j = bid - 1; j >= 0; j--) {
            int f;
            do { f = g_flag[j]; } while (f == 0);
            if (f == 2) { excl += g_bpre[j]; break; }
            excl += g_bsum[j];
        }
        g_bpre[bid] = excl + total;
        __threadfence();
        g_flag[bid] = 2;
        s_off = excl;
    }
    __syncthreads();
    if (i < Nn) {
        int r = s[threadIdx.x] - v + s_off;
        g_rowptr[i] = r;
        g_cursor[i] = r;
        g_cnt[i] = 0;                        // ready for next replay
    }
    if (i == 0) g_rowptr[Nn] = E;
}

// ---------------- L3: fill CSR (+ reset lookback flags) -----------------------
__global__ void fill_kernel(int E) {
    int e = blockIdx.x * blockDim.x + threadIdx.x;
    if (e < 256) g_flag[e] = 0;
    if (e < E) {
        int pos = atomicAdd(&g_cursor[g_dst[e]], 1);
        g_esrc[pos] = g_src[e];
    }
}

// ---------------- L4: gather-mean agg1 — 2 nodes/warp, uint4 loads ------------
__global__ void agg1_kernel(int Nn) {
    int gw = (blockIdx.x * blockDim.x + threadIdx.x) >> 5;
    int lane = threadIdx.x & 31;
    int node = gw * 2 + (lane >> 4);
    int hl = lane & 15;                      // lane within half-warp
    if (node >= Nn) return;
    int s0 = g_rowptr[node], s1 = g_rowptr[node + 1];
    float acc[8] = {0.f, 0.f, 0.f, 0.f, 0.f, 0.f, 0.f, 0.f};
    for (int e = s0; e < s1; e++) {
        int src = g_esrc[e];
        uint4 u = *(const uint4*)(g_a1 + (size_t)src * 256 + 128 + hl * 8);
        float2 f0 = __half22float2(*(__half2*)&u.x);
        float2 f1 = __half22float2(*(__half2*)&u.y);
        float2 f2 = __half22float2(*(__half2*)&u.z);
        float2 f3 = __half22float2(*(__half2*)&u.w);
        acc[0] += f0.x; acc[1] += f0.y; acc[2] += f1.x; acc[3] += f1.y;
        acc[4] += f2.x; acc[5] += f2.y; acc[6] += f3.x; acc[7] += f3.y;
    }
    float inv = 1.f / fmaxf((float)(s1 - s0), 1.f);
    __half2 p0 = __floats2half2_rn(acc[0] * inv, acc[1] * inv);
    __half2 p1 = __floats2half2_rn(acc[2] * inv, acc[3] * inv);
    __half2 p2 = __floats2half2_rn(acc[4] * inv, acc[5] * inv);
    __half2 p3 = __floats2half2_rn(acc[6] * inv, acc[7] * inv);
    uint4 o;
    o.x = *(uint32_t*)&p0; o.y = *(uint32_t*)&p1;
    o.z = *(uint32_t*)&p2; o.w = *(uint32_t*)&p3;
    *(uint4*)(g_a1 + (size_t)node * 256 + hl * 8) = o;
}

// ---------------- L5/L6: HMMA fp16 GEMM ---------------------------------------
#define ROWB 144
#define TILE_BYTES (128 * ROWB)

__device__ __forceinline__ void load_one(uint32_t sT, const __half* __restrict__ T,
                                         int row0, int k0, int tid) {
    int row = tid >> 1;
    const char* src = (const char*)(T + (size_t)(row0 + row) * 256 + k0) + (tid & 1) * 64;
    uint32_t d = sT + row * ROWB + (tid & 1) * 64;
#pragma unroll
    for (int j = 0; j < 4; j++) cp16(d + j * 16, src + j * 16);
}

// MODE 1: D[.,256] = [agg1|x] @ W1 ; +b1, relu -> g_h (fp16)
// MODE 2: D[.,128] = h @ [W2l|W2r] ; fp16 -> g_t2 (t cols 0-63, o2 cols 64-127)
template <int MODE>
__global__ __launch_bounds__(256, 2)
void mma_kernel(const float* __restrict__ bias, int Nn) {
    extern __shared__ char sm[];
    const uint32_t smb = smem_u32(sm);
    const uint32_t Abuf[2] = { smb, smb + TILE_BYTES };
    const uint32_t Bbuf[2] = { smb + 2 * TILE_BYTES, smb + 3 * TILE_BYTES };

    const int tid = threadIdx.x;
    const int wid = tid >> 5;
    const int lane = tid & 31;
    const int m0 = blockIdx.x * 128;
    const int n0 = blockIdx.y * 128;

    const __half* A = (MODE == 1) ? g_a1 : g_h;
    const __half* B = (MODE == 1) ? g_W1 : g_W2;

    const int wm = (wid >> 2) * 64;
    const int wn = (wid & 3) * 32;
    const int lrow = lane & 15;
    const int lcol8 = (lane >> 4) * 8;

    float acc[4][4][4];
#pragma unroll
    for (int i = 0; i < 4; i++)
#pragma unroll
        for (int j = 0; j < 4; j++)
#pragma unroll
            for (int q = 0; q < 4; q++) acc[i][j][q] = 0.f;

    load_one(Abuf[0], A, m0, 0, tid);
    load_one(Bbuf[0], B, n0, 0, tid);
    cp_commit();
    cp_wait0();
    __syncthreads();

    for (int s = 0; s < 4; s++) {
        int sn = s + 1;
        if (sn < 4) {
            load_one(Abuf[sn & 1], A, m0, sn * 64, tid);
            load_one(Bbuf[sn & 1], B, n0, sn * 64, tid);
            cp_commit();
        }
        uint32_t sA = Abuf[s & 1], sB = Bbuf[s & 1];
#pragma unroll
        for (int ks = 0; ks < 4; ks++) {
            int kb = ks * 16 + lcol8;
            uint32_t a[4][4], b[2][4];
#pragma unroll
            for (int mt = 0; mt < 4; mt++)
                ldsm_x4(a[mt][0], a[mt][1], a[mt][2], a[mt][3],
                        sA + (wm + mt * 16 + lrow) * ROWB + kb * 2);
#pragma unroll
            for (int p = 0; p < 2; p++)
                ldsm_x4(b[p][0], b[p][1], b[p][2], b[p][3],
                        sB + (wn + p * 16 + lrow) * ROWB + kb * 2);
#pragma unroll
            for (int mt = 0; mt < 4; mt++)
#pragma unroll
                for (int nt = 0; nt < 4; nt++)
                    mma_f16(acc[mt][nt], a[mt], b[nt >> 1][nt & 1], b[nt >> 1][(nt & 1) + 2]);
        }
        if (sn < 4) cp_wait0();
        __syncthreads();
    }

#pragma unroll
    for (int mt = 0; mt < 4; mt++) {
        int r0 = m0 + wm + mt * 16 + (lane >> 2);
#pragma unroll
        for (int nt = 0; nt < 4; nt++) {
            int colL = wn + nt * 8 + (lane & 3) * 2;
            if (MODE == 1) {
                int col = n0 + colL;
                float bb0 = __ldg(bias + col), bb1 = __ldg(bias + col + 1);
#pragma unroll
                for (int h = 0; h < 2; h++) {
                    int r = r0 + h * 8;
                    if (r < Nn) {
                        float v0 = fmaxf(acc[mt][nt][2 * h + 0] + bb0, 0.f);
                        float v1 = fmaxf(acc[mt][nt][2 * h + 1] + bb1, 0.f);
                        __half2 p = __floats2half2_rn(v0, v1);
                        *(uint32_t*)(g_h + (size_t)r * 256 + col) = *(uint32_t*)&p;
                    }
                }
            } else {
#pragma unroll
                for (int h = 0; h < 2; h++) {
                    int r = r0 + h * 8;
                    if (r < Nn) {
                        __half2 p = __floats2half2_rn(acc[mt][nt][2 * h + 0],
                                                      acc[mt][nt][2 * h + 1]);
                        *(uint32_t*)(g_t2 + (size_t)r * 128 + colL) = *(uint32_t*)&p;
                    }
                }
            }
        }
    }
}

// ---------------- L7: agg2 + final — 2 nodes/warp, uint2 loads ----------------
// out[node] = mean(gather t) + o2[node] + b2 ; t = g_t2 cols 0-63, o2 = 64-127
__global__ void agg2_final_kernel(const float* __restrict__ b2,
                                  float* __restrict__ out, int Nn) {
    int gw = (blockIdx.x * blockDim.x + threadIdx.x) >> 5;
    int lane = threadIdx.x & 31;
    int node = gw * 2 + (lane >> 4);
    int hl = lane & 15;
    if (node >= Nn) return;
    int s0 = g_rowptr[node], s1 = g_rowptr[node + 1];
    float acc[4] = {0.f, 0.f, 0.f, 0.f};
    for (int e = s0; e < s1; e++) {
        int src = g_esrc[e];
        uint2 u = *(const uint2*)(g_t2 + (size_t)src * 128 + hl * 4);
        float2 f0 = __half22float2(*(__half2*)&u.x);
        float2 f1 = __half22float2(*(__half2*)&u.y);
        acc[0] += f0.x; acc[1] += f0.y; acc[2] += f1.x; acc[3] += f1.y;
    }
    float inv = 1.f / fmaxf((float)(s1 - s0), 1.f);
    uint2 uo = *(const uint2*)(g_t2 + (size_t)node * 128 + 64 + hl * 4);
    float2 o0 = __half22float2(*(__half2*)&uo.x);
    float2 o1 = __half22float2(*(__half2*)&uo.y);
    float4 bb = *(const float4*)(b2 + hl * 4);
    float4 v;
    v.x = acc[0] * inv + o0.x + bb.x;
    v.y = acc[1] * inv + o0.y + bb.y;
    v.z = acc[2] * inv + o1.x + bb.z;
    v.w = acc[3] * inv + o1.y + bb.w;
    *(float4*)(out + (size_t)node * 64 + hl * 4) = v;
}

// ---------------- launch --------------------------------------------------------
extern "C" void kernel_launch(void* const* d_in, const int* in_sizes, int n_in,
                              void* d_out, int out_size) {
    const float* x   = (const float*)d_in[0];
    const int*   ei  = (const int*)d_in[1];      // staged int32 (verified empirically)
    const float* W1l = (const float*)d_in[2];
    const float* b1  = (const float*)d_in[3];
    const float* W1r = (const float*)d_in[4];
    const float* W2l = (const float*)d_in[5];
    const float* b2  = (const float*)d_in[6];
    const float* W2r = (const float*)d_in[7];
    float*       out = (float*)d_out;

    const int Nn = in_sizes[0] / 128;
    const int E  = in_sizes[1] / 2;
    const int nb = (Nn + 511) / 512;

    const int SMEM = 4 * TILE_BYTES;   // 73728
    cudaFuncSetAttribute(mma_kernel<1>, cudaFuncAttributeMaxDynamicSharedMemorySize, SMEM);
    cudaFuncSetAttribute(mma_kernel<2>, cudaFuncAttributeMaxDynamicSharedMemorySize, SMEM);

    const int EB = ((E + 255) / 256) * 256;
    const int prepThreads = EB + 98304 + Nn * 32;
    prep_kernel<<<(prepThreads + 255) / 256, 256>>>(ei, E, Nn, W1l, W1r, W2l, W2r, x);
    scan_kernel<<<nb, 512>>>(Nn, E);
    fill_kernel<<<(E + 255) / 256, 256>>>(E);
    agg1_kernel<<<(Nn * 16 + 255) / 256, 256>>>(Nn);

    const int grid = (Nn + 127) / 128;
    mma_kernel<1><<<dim3(grid, 2), 256, SMEM>>>(b1, Nn);
    mma_kernel<2><<<dim3(grid, 1), 256, SMEM>>>(b2, Nn);
    agg2_final_kernel<<<(Nn * 16 + 255) / 256, 256>>>(b2, out, Nn);
}